// round 10
// baseline (speedup 1.0000x reference)
#include <cuda_runtime.h>

// ============================================================================
// AdapterSubnet top-k binary mask via sampled-bracket exact radix selection.
// 3-kernel pipeline with in-kernel software grid barriers:
//   asn_front: zero -> bar -> sampled coarse hist -> bar -> band select
//   asn_mark : full read/write pass, candidate compaction, h1 histogram
//   asn_back : h1 scan + h3 fill -> bar -> candidate resolve -> bar -> ties
//
// key(x) = float_as_uint(|x|); coarse bin = key >> 18 (8192 bins);
// band = 3 coarse bins around sampled threshold bin; rel = key - lo_key.
// Tie rule (stable argsort ascending, keep tail): among elements with
// key == threshold, keep the ones with LARGEST original indices.
// ============================================================================

#define SHIFT 18
#define NB_COARSE (1 << (31 - SHIFT))   // 8192
#define RANGE_COARSE 3
#define RB (RANGE_COARSE << SHIFT)      // 786,432 rel values
#define H1BINS (RB >> 7)                // 6144
#define CAND_CAP (1u << 20)             // 1,048,576 candidates per matrix
#define EQ_CAP 65536
#define NWARP 16                        // 512 threads in asn_mark
#define WBUF 96                         // per-warp staging entries
#define WFLUSH 64                       // flush threshold

#define FB_X 128                        // front blocks per matrix
#define FB_N (FB_X * 2)
#define BB_X 148                        // back blocks per matrix
#define BB_N (BB_X * 2)

__device__ unsigned g_shist[2][NB_COARSE];
__device__ unsigned g_h1[2][H1BINS];
__device__ unsigned g_h3[2][128];
__device__ unsigned long long g_cand[2][CAND_CAP];
__device__ unsigned g_eq[2][EQ_CAP];
__device__ unsigned g_candcnt[2];
__device__ unsigned g_eqcnt[2];
__device__ unsigned g_cntabove[2];
__device__ unsigned g_lokey[2], g_hikey[2];
__device__ unsigned g_barA, g_barB;     // epoch grid-barrier counters

// ---------------------------------------------------------------------------
// Epoch-based software grid barrier. Counter is monotonic; each call adds nb,
// so no reset is needed across graph replays. All nb blocks must be resident.
// Post-barrier cross-block data must be read with __ldcg (L1 not coherent).
__device__ __forceinline__ void grid_bar(unsigned* ctr, unsigned nb) {
    __syncthreads();
    if (threadIdx.x == 0) {
        __threadfence();
        unsigned my = atomicAdd(ctr, 1u);
        unsigned target = (my / nb + 1u) * nb;
        while (atomicAdd(ctr, 0u) < target) __nanosleep(64);
    }
    __syncthreads();
}

// ---------------------------------------------------------------------------
// Block-wide (256-thread) inclusive suffix scan; buf has 512 entries.
__device__ unsigned* suffix_scan_256(unsigned v, unsigned* buf) {
    unsigned t = threadIdx.x;
    unsigned* a = buf;
    unsigned* b = buf + 256;
    a[t] = v;
    __syncthreads();
    for (int d = 1; d < 256; d <<= 1) {
        unsigned x = a[t] + ((t + d < 256u) ? a[t + d] : 0u);
        b[t] = x;
        __syncthreads();
        unsigned* tmp = a; a = b; b = tmp;
    }
    return a;
}

// ---------------------------------------------------------------------------
// FRONT: zero state -> sampled coarse histogram -> band selection.
// grid = (FB_X, 2), 256 threads. All FB_N blocks co-resident (32KB smem -> 7/SM).
__global__ void __launch_bounds__(256) asn_front(const float* in0, const float* in1,
                                                 int n, unsigned m_samp) {
    int mat = blockIdx.y;
    const float* in = mat ? in1 : in0;
    __shared__ unsigned sh[NB_COARSE];

    // ---- phase 0: zero all per-run state ----
    unsigned bid = blockIdx.y * gridDim.x + blockIdx.x;
    unsigned id = bid * 256u + threadIdx.x;
    unsigned gs = FB_N * 256u;
    unsigned* ps = &g_shist[0][0];
    for (unsigned i = id; i < 2 * NB_COARSE; i += gs) ps[i] = 0u;
    unsigned* ph1 = &g_h1[0][0];
    for (unsigned i = id; i < 2 * H1BINS; i += gs) ph1[i] = 0u;
    unsigned* ph3 = &g_h3[0][0];
    for (unsigned i = id; i < 256; i += gs) ph3[i] = 0u;
    if (id < 2) {
        g_candcnt[id] = 0u;
        g_eqcnt[id] = 0u;
        g_cntabove[id] = 0u;
    }
    grid_bar(&g_barA, FB_N);

    // ---- phase 1: sampled coarse histogram (S = n/64 samples, coalesced:
    //      32 consecutive floats per 2048-element group = one full 128B line/warp)
    for (int i = threadIdx.x; i < NB_COARSE; i += 256) sh[i] = 0u;
    __syncthreads();
    int S = n >> 6;
    for (int s = blockIdx.x * 256 + threadIdx.x; s < S; s += FB_X * 256) {
        int idx = ((s >> 5) << 11) | (s & 31);
        unsigned u = __float_as_uint(in[idx]) & 0x7fffffffu;
        atomicAdd(&sh[u >> SHIFT], 1u);
    }
    __syncthreads();
    for (int i = threadIdx.x; i < NB_COARSE; i += 256)
        if (sh[i]) atomicAdd(&g_shist[mat][i], sh[i]);
    grid_bar(&g_barA, FB_N);

    // ---- phase 2: band selection, block (0, mat) only ----
    if (blockIdx.x == 0) {
        unsigned t = threadIdx.x;
        __shared__ int s_B;
        unsigned hb[32];
        unsigned v = 0;
#pragma unroll
        for (int j = 0; j < 32; j++) {
            hb[j] = __ldcg(&g_shist[mat][t * 32 + j]);  // bypass stale L1
            v += hb[j];
        }
        unsigned* a = suffix_scan_256(v, sh);
        unsigned need = m_samp;
        if (a[t] >= need && (t == 255u || a[t + 1] < need)) {
            unsigned acc = (t == 255u) ? 0u : a[t + 1];
            for (int j = 31; j >= 0; j--) {
                acc += hb[j];
                if (acc >= need) { s_B = (int)(t * 32 + (unsigned)j); break; }
            }
        }
        __syncthreads();
        if (t == 0) {
            int B = s_B;
            int lo = B - 1;
            if (lo < 0) lo = 0;
            int hi = lo + RANGE_COARSE;
            if (hi > NB_COARSE) { hi = NB_COARSE; lo = hi - RANGE_COARSE; }
            g_lokey[mat] = (unsigned)lo << SHIFT;
            g_hikey[mat] = (unsigned)hi << SHIFT;
        }
    }
}

// ---------------------------------------------------------------------------
// Warp-private candidate push + flush (no block barriers).
__device__ __forceinline__ void asn_push(
    int mat, int w, unsigned lane,
    unsigned long long (*s_buf)[WBUF], unsigned* s_wcnt,
    unsigned long long pack)
{
    unsigned act = __activemask();
    unsigned lml = (1u << lane) - 1u;
    int leader = __ffs(act) - 1;
    unsigned cnt = __popc(act);
    unsigned rank = __popc(act & lml);
    unsigned p0 = s_wcnt[w];            // warp-private; all active lanes read same
    s_buf[w][p0 + rank] = pack;
    unsigned fcnt = p0 + cnt;
    if ((int)lane == leader) s_wcnt[w] = fcnt;
    if (fcnt >= WFLUSH) {
        __syncwarp(act);                 // make s_buf writes visible warp-wide
        unsigned base;
        if ((int)lane == leader) base = atomicAdd(&g_candcnt[mat], fcnt);
        base = __shfl_sync(act, base, leader);
        for (unsigned j = rank; j < fcnt; j += cnt) {
            unsigned slot = base + j;
            if (slot < CAND_CAP) g_cand[mat][slot] = s_buf[w][j];
        }
        if ((int)lane == leader) s_wcnt[w] = 0u;
    }
}

// ---------------------------------------------------------------------------
// Per-float4 processing for the mark pass.
__device__ __forceinline__ void asn_proc4(
    float4 v, unsigned base_idx, unsigned lo, unsigned hi, unsigned bw,
    int mat, int w, unsigned lane,
    unsigned long long (*s_buf)[WBUF], unsigned* s_wcnt,
    unsigned& myAbove, float4& ov)
{
    float vv[4] = {v.x, v.y, v.z, v.w};
    float o[4];
#pragma unroll
    for (int c = 0; c < 4; c++) {
        unsigned u = __float_as_uint(vv[c]) & 0x7fffffffu;
        unsigned rel = u - lo;
        bool above = (u >= hi);
        o[c] = above ? 1.0f : 0.0f;
        myAbove += above ? 1u : 0u;
        if (rel < bw) {   // candidate band [lo, hi)
            atomicAdd(&g_h1[mat][rel >> 7], 1u);   // 24KB, L2-resident
            asn_push(mat, w, lane, s_buf, s_wcnt,
                     ((unsigned long long)(base_idx + (unsigned)c) << 32) | rel);
        }
    }
    ov = make_float4(o[0], o[1], o[2], o[3]);
}

// ---------------------------------------------------------------------------
// Main pass: read input, write definite 1s/0s, compact band candidates,
// level-1 histogram (L2-resident), exact count of elements >= hi_key.
// MLP=2: two independent float4 loads in flight per thread.
__global__ void __launch_bounds__(512) asn_mark(const float4* in0, const float4* in1,
                                                float* out, int n4, int n) {
    int mat = blockIdx.y;
    const float4* in = mat ? in1 : in0;
    float4* out4 = reinterpret_cast<float4*>(out) + (size_t)mat * n4;
    unsigned lo = g_lokey[mat], hi = g_hikey[mat];
    unsigned bw = hi - lo;

    __shared__ unsigned long long s_buf[NWARP][WBUF];
    __shared__ unsigned s_wcnt[NWARP];
    int w = threadIdx.x >> 5;
    unsigned lane = threadIdx.x & 31u;
    if (lane == 0) s_wcnt[w] = 0u;
    __syncwarp();

    unsigned myAbove = 0;
    unsigned gsize = gridDim.x * blockDim.x;
    unsigned gid = blockIdx.x * blockDim.x + threadIdx.x;

    for (unsigned i = gid; i < (unsigned)n4; i += 2u * gsize) {
        unsigned i2 = i + gsize;
        bool h2 = i2 < (unsigned)n4;
        float4 va = in[i];                       // both loads issue back-to-back
        float4 vb;
        if (h2) vb = in[i2];
        float4 oa, ob;
        asn_proc4(va, i * 4u, lo, hi, bw, mat, w, lane, s_buf, s_wcnt, myAbove, oa);
        out4[i] = oa;
        if (h2) {
            asn_proc4(vb, i2 * 4u, lo, hi, bw, mat, w, lane, s_buf, s_wcnt, myAbove, ob);
            out4[i2] = ob;
        }
    }

    // tail elements (n % 4), processed by block (0, mat)
    if (blockIdx.x == 0) {
        int start = n4 << 2;
        for (int i = start + (int)threadIdx.x; i < n; i += (int)blockDim.x) {
            const float* inf = (const float*)in;
            float* o = (float*)out4;
            unsigned u = __float_as_uint(inf[i]) & 0x7fffffffu;
            unsigned rel = u - lo;
            bool above = (u >= hi);
            o[i] = above ? 1.0f : 0.0f;
            myAbove += above ? 1u : 0u;
            if (rel < bw) {
                atomicAdd(&g_h1[mat][rel >> 7], 1u);
                asn_push(mat, w, lane, s_buf, s_wcnt,
                         ((unsigned long long)(unsigned)i << 32) | rel);
            }
        }
    }

    // final per-warp flush (full warp active here)
    {
        __syncwarp();
        unsigned fcnt = s_wcnt[w];
        if (fcnt) {
            unsigned base;
            if (lane == 0) base = atomicAdd(&g_candcnt[mat], fcnt);
            base = __shfl_sync(0xffffffffu, base, 0);
            for (unsigned j = lane; j < fcnt; j += 32u) {
                unsigned slot = base + j;
                if (slot < CAND_CAP) g_cand[mat][slot] = s_buf[w][j];
            }
        }
    }

    // block-level reduce of exact above-count (single global atomic per block)
    __shared__ unsigned s_red[NWARP];
    unsigned wsum = myAbove;
#pragma unroll
    for (int d = 16; d; d >>= 1) wsum += __shfl_down_sync(0xffffffffu, wsum, d);
    if (lane == 0) s_red[w] = wsum;
    __syncthreads();
    if (threadIdx.x == 0) {
        unsigned tot = 0;
        for (int k = 0; k < NWARP; k++) tot += s_red[k];
        atomicAdd(&g_cntabove[mat], tot);
    }
}

// ---------------------------------------------------------------------------
// BACK: level-1 scan + h3 fill -> bar -> candidate resolve -> bar -> ties.
// grid = (BB_X, 2), 256 threads. All BB_N blocks co-resident.
__global__ void __launch_bounds__(256) asn_back(float* out, int n, unsigned m) {
    int mat = blockIdx.y;
    float* o = out + (size_t)mat * n;
    unsigned t = threadIdx.x;
    unsigned lane = t & 31u;
    __shared__ unsigned buf[512];
    __shared__ unsigned sh_B2, sh_need2;

    // ---- phase 1: find level-1 winning bin B2 + need2 (redundant per block,
    //      h1 is L2-cached), then filter candidates into h3[128] ----
    unsigned cAbove = g_cntabove[mat];   // written by asn_mark: kernel boundary
    unsigned cand = g_candcnt[mat];
    long long need_ll = (long long)m - (long long)cAbove;
    int vf = 0;                          // uniform across all threads/blocks
    if (need_ll < 1) vf = 1;
    else if (need_ll > (long long)cand || cand > CAND_CAP) vf = 2;
    unsigned ccnt = cand > CAND_CAP ? CAND_CAP : cand;

    if (vf == 0) {
        unsigned need = (unsigned)need_ll;
        unsigned hb[24];
        unsigned v = 0;
#pragma unroll
        for (int j = 0; j < 24; j++) { hb[j] = g_h1[mat][t * 24 + j]; v += hb[j]; }
        unsigned* a = suffix_scan_256(v, buf);
        if (a[t] >= need && (t == 255u || a[t + 1] < need)) {
            unsigned acc = (t == 255u) ? 0u : a[t + 1];
            for (int j = 23; j >= 0; j--) {
                acc += hb[j];
                if (acc >= need) {
                    sh_B2 = t * 24u + (unsigned)j;
                    sh_need2 = need - (acc - hb[j]);
                    break;
                }
            }
        }
        __syncthreads();
        unsigned B2 = sh_B2;
        for (unsigned i = blockIdx.x * 256u + t; i < ccnt; i += BB_X * 256u) {
            unsigned rel = (unsigned)(g_cand[mat][i] & 0xffffffffu);
            if ((rel >> 7) == B2) atomicAdd(&g_h3[mat][rel & 127u], 1u);
        }
    }
    grid_bar(&g_barB, BB_N);

    // ---- phase 2: compute exact threshold F from h3 (redundant per block),
    //      then resolve candidates: rel > F -> 1; rel == F -> tie buffer ----
    int F;
    unsigned needK;
    if (vf == 1) { F = 0x7fffffff; needK = 0u; }
    else if (vf == 2) { F = -1; needK = 0u; }
    else {
        __shared__ unsigned sh3[128];
        __shared__ int sFv;
        __shared__ unsigned sNk;
        if (t < 128) sh3[t] = __ldcg(&g_h3[mat][t]);   // bypass stale L1
        __syncthreads();
        if (t == 0) {
            unsigned need2 = sh_need2, B2 = sh_B2;
            unsigned acc = 0;
            sFv = 0x7fffffff; sNk = 0u;
            for (int b = 127; b >= 0; b--) {
                acc += sh3[b];
                if (acc >= need2) {
                    sFv = (int)(B2 * 128u + (unsigned)b);
                    sNk = need2 - (acc - sh3[b]);
                    break;
                }
            }
        }
        __syncthreads();
        F = sFv; needK = sNk;
    }
    for (unsigned i = blockIdx.x * 256u + t; i < ccnt; i += BB_X * 256u) {
        unsigned long long e = g_cand[mat][i];
        int rel = (int)(unsigned)(e & 0xffffffffu);
        unsigned idx = (unsigned)(e >> 32);
        if (rel > F) {
            o[idx] = 1.0f;
        } else if (rel == F) {
            unsigned act = __activemask();
            int leader = __ffs(act) - 1;
            unsigned p0;
            if ((int)lane == leader) p0 = atomicAdd(&g_eqcnt[mat], __popc(act));
            p0 = __shfl_sync(act, p0, leader);
            unsigned p = p0 + __popc(act & ((1u << lane) - 1u));
            if (p < EQ_CAP) g_eq[mat][p] = idx;
        }
    }
    grid_bar(&g_barB, BB_N);

    // ---- phase 3: tie resolution, block (0, mat). Keep needK LARGEST indices
    //      among exact-threshold elements (stable ascending argsort keeps the
    //      tail => largest original indices). ----
    if (blockIdx.x != 0) return;
    unsigned cnt = __ldcg(&g_eqcnt[mat]);
    if (cnt > EQ_CAP) cnt = EQ_CAP;
    if (cnt == 0u || needK == 0u) return;
    if (needK >= cnt) {
        for (unsigned i = t; i < cnt; i += 256u) o[__ldcg(&g_eq[mat][i])] = 1.0f;
        return;
    }
    __shared__ unsigned s_red[8];
    __shared__ unsigned s_lo, s_hi;
    if (t == 0) { s_lo = 0u; s_hi = (unsigned)n; }
    __syncthreads();
    while (true) {
        unsigned lo = s_lo, hi = s_hi;
        if (lo + 1u >= hi) break;
        unsigned mid = lo + (hi - lo) / 2u;
        unsigned c = 0;
        for (unsigned i = t; i < cnt; i += 256u)
            c += (__ldcg(&g_eq[mat][i]) >= mid) ? 1u : 0u;
#pragma unroll
        for (int d = 16; d; d >>= 1) c += __shfl_down_sync(0xffffffffu, c, d);
        if (lane == 0) s_red[t >> 5] = c;
        __syncthreads();
        if (t == 0) {
            unsigned tot = 0;
            for (int k = 0; k < 8; k++) tot += s_red[k];
            if (tot >= needK) s_lo = mid; else s_hi = mid;
        }
        __syncthreads();
    }
    unsigned cut = s_lo;
    for (unsigned i = t; i < cnt; i += 256u) {
        unsigned idx = __ldcg(&g_eq[mat][i]);
        if (idx >= cut) o[idx] = 1.0f;
    }
}

// ===========================================================================
extern "C" void kernel_launch(void* const* d_in, const int* in_sizes, int n_in,
                              void* d_out, int out_size) {
    const float* in0 = (const float*)d_in[0];
    const float* in1 = (const float*)d_in[1];
    float* out = (float*)d_out;
    int n = in_sizes[0];
    int n4 = n >> 2;

    // m = n - int(0.9 * n), matching python int() truncation semantics
    int j = (int)((1.0 - 0.1) * (double)n);
    unsigned m = (unsigned)(n - j);
    int S = n >> 6;
    unsigned m_samp = (unsigned)((double)m * (double)S / (double)n);

    asn_front<<<dim3(FB_X, 2), 256>>>(in0, in1, n, m_samp);
    asn_mark<<<dim3(592, 2), 512>>>((const float4*)in0, (const float4*)in1, out, n4, n);
    asn_back<<<dim3(BB_X, 2), 256>>>(out, n, m);
}